// round 1
// baseline (speedup 1.0000x reference)
#include <cuda_runtime.h>
#include <cuda_bf16.h>
#include <cstddef>

// ---------------- fixed problem constants ----------------
#define NTOK 2048
#define DMODEL 1280
#define NHEAD 16
#define KDIM 80
#define HALFK 40
#define NLAYER 4
#define FDIM 5120
#define GPOS 48
#define OUTD 2048
#define TPI 512      // tokens per image (1*16*32)
#define NIMG 4

// ---------------- scratch (device globals; no runtime alloc) ----------------
__device__ float g_x[NTOK * DMODEL];
__device__ float g_hdn[NTOK * DMODEL];
__device__ float g_qkv[NTOK * 3 * DMODEL];
__device__ float g_scores[(size_t)NHEAD * NTOK * TPI];   // 64 MB
__device__ float g_obuf[NTOK * DMODEL];
__device__ float g_ff[NTOK * FDIM];                      // 40 MB
__device__ float g_cos[NTOK * HALFK];
__device__ float g_sin[NTOK * HALFK];
__device__ int g_row[NTOK], g_col[NTOK], g_h[NTOK], g_w[NTOK];

// ---------------- helpers ----------------
__device__ __forceinline__ float gelu_tanh(float v) {
    const float c = 0.7978845608028654f;
    float t = tanhf(c * (v + 0.044715f * v * v * v));
    return 0.5f * v * (1.0f + t);
}

__device__ __forceinline__ float warp_sum(float v) {
    #pragma unroll
    for (int o = 16; o > 0; o >>= 1) v += __shfl_xor_sync(0xffffffffu, v, o);
    return v;
}
__device__ __forceinline__ float warp_max(float v) {
    #pragma unroll
    for (int o = 16; o > 0; o >>= 1) v = fmaxf(v, __shfl_xor_sync(0xffffffffu, v, o));
    return v;
}

// ---------------- token coords ----------------
__global__ void coords_kernel(const int* __restrict__ grid, int n_imgs) {
    int t = blockIdx.x * blockDim.x + threadIdx.x;
    if (t >= NTOK) return;
    int acc = 0, local = 0, h = 1, w = 1;
    for (int i = 0; i < n_imgs; i++) {
        int tpi = grid[i * 3] * grid[i * 3 + 1] * grid[i * 3 + 2];
        if (t >= acc && t < acc + tpi) {
            local = t - acc; h = grid[i * 3 + 1]; w = grid[i * 3 + 2];
        }
        acc += tpi;
    }
    int spatial = local % (h * w);
    int group = spatial / 4, intra = spatial % 4;   // merge_size = 2
    int mw = w / 2;
    g_row[t] = (group / mw) * 2 + intra / 2;
    g_col[t] = (group % mw) * 2 + intra % 2;
    g_h[t] = h; g_w[t] = w;
}

// ---------------- rope cos/sin table ----------------
__global__ void ropetab_kernel() {
    int id = blockIdx.x * blockDim.x + threadIdx.x;
    if (id >= NTOK * HALFK) return;
    int n = id / HALFK, j = id % HALFK;
    int jj = j % 20;
    float pos = (float)((j < 20) ? g_row[n] : g_col[n]);
    float inv_freq = powf(10000.0f, -(float)jj / 20.0f);
    float f = pos * inv_freq;
    g_cos[id] = cosf(f);
    g_sin[id] = sinf(f);
}

// ---------------- bilinear pos-embed add ----------------
__global__ void posembed_kernel(const float* __restrict__ pos_embed, float* __restrict__ x) {
    int n = blockIdx.x;
    int row = g_row[n], col = g_col[n], h = g_h[n], w = g_w[n];
    float rf = (h > 1) ? (float)row * (float)(GPOS - 1) / (float)(h - 1 > 1 ? h - 1 : 1) : 0.0f;
    float cf = (w > 1) ? (float)col * (float)(GPOS - 1) / (float)(w - 1 > 1 ? w - 1 : 1) : 0.0f;
    int r0 = (int)floorf(rf), c0 = (int)floorf(cf);
    int r1 = min(r0 + 1, GPOS - 1), c1 = min(c0 + 1, GPOS - 1);
    float wr = rf - (float)r0, wc = cf - (float)c0;
    float w00 = (1 - wr) * (1 - wc), w01 = (1 - wr) * wc, w10 = wr * (1 - wc), w11 = wr * wc;
    const float* p00 = pos_embed + (size_t)(r0 * GPOS + c0) * DMODEL;
    const float* p01 = pos_embed + (size_t)(r0 * GPOS + c1) * DMODEL;
    const float* p10 = pos_embed + (size_t)(r1 * GPOS + c0) * DMODEL;
    const float* p11 = pos_embed + (size_t)(r1 * GPOS + c1) * DMODEL;
    float* xr = x + (size_t)n * DMODEL;
    for (int d = threadIdx.x; d < DMODEL; d += blockDim.x)
        xr[d] += p00[d] * w00 + p01[d] * w01 + p10[d] * w10 + p11[d] * w11;
}

// ---------------- two-pass layernorm ----------------
__global__ void layernorm_kernel(const float* __restrict__ x, const float* __restrict__ s,
                                 const float* __restrict__ b, float* __restrict__ out, int cols) {
    int r = blockIdx.x, tid = threadIdx.x;
    const float* xr = x + (size_t)r * cols;
    __shared__ float red[8];
    float sum = 0.0f;
    for (int c = tid; c < cols; c += 256) sum += xr[c];
    sum = warp_sum(sum);
    if ((tid & 31) == 0) red[tid >> 5] = sum;
    __syncthreads();
    float tot = 0.0f;
    #pragma unroll
    for (int i = 0; i < 8; i++) tot += red[i];
    float mu = tot / (float)cols;
    __syncthreads();
    float vs = 0.0f;
    for (int c = tid; c < cols; c += 256) { float d = xr[c] - mu; vs += d * d; }
    vs = warp_sum(vs);
    if ((tid & 31) == 0) red[tid >> 5] = vs;
    __syncthreads();
    float vtot = 0.0f;
    #pragma unroll
    for (int i = 0; i < 8; i++) vtot += red[i];
    float inv = rsqrtf(vtot / (float)cols + 1e-6f);
    float* orow = out + (size_t)r * cols;
    for (int c = tid; c < cols; c += 256)
        orow[c] = (xr[c] - mu) * inv * s[c] + b[c];
}

// ---------------- generic SGEMM: C = A @ W + bias (+res) (+gelu) ----------------
// MM % 64 == 0, NN % 64 == 0, KK % 16 == 0
__global__ void gemm_kernel(const float* __restrict__ A, const float* __restrict__ W,
                            const float* __restrict__ bias, const float* __restrict__ res,
                            float* __restrict__ C, int MM, int NN, int KK, int epi) {
    __shared__ float As[16][64];
    __shared__ float Bs[16][64];
    const int tid = threadIdx.x;
    const int tx = tid & 15, ty = tid >> 4;
    const int m0 = blockIdx.y * 64, n0 = blockIdx.x * 64;
    const int lm = tid >> 2, lk = (tid & 3) << 2;    // A tile loader
    const int wk = tid >> 4, wn = (tid & 15) << 2;   // W tile loader
    float acc[4][4] = {};
    for (int k0 = 0; k0 < KK; k0 += 16) {
        float4 a = *(const float4*)(A + (size_t)(m0 + lm) * KK + k0 + lk);
        As[lk + 0][lm] = a.x; As[lk + 1][lm] = a.y;
        As[lk + 2][lm] = a.z; As[lk + 3][lm] = a.w;
        *(float4*)(&Bs[wk][wn]) = *(const float4*)(W + (size_t)(k0 + wk) * NN + n0 + wn);
        __syncthreads();
        #pragma unroll
        for (int k = 0; k < 16; ++k) {
            float av[4], bv[4];
            #pragma unroll
            for (int i = 0; i < 4; ++i) av[i] = As[k][ty * 4 + i];
            #pragma unroll
            for (int j = 0; j < 4; ++j) bv[j] = Bs[k][tx * 4 + j];
            #pragma unroll
            for (int i = 0; i < 4; ++i)
                #pragma unroll
                for (int j = 0; j < 4; ++j)
                    acc[i][j] = fmaf(av[i], bv[j], acc[i][j]);
        }
        __syncthreads();
    }
    #pragma unroll
    for (int i = 0; i < 4; ++i) {
        int r = m0 + ty * 4 + i;
        #pragma unroll
        for (int j = 0; j < 4; ++j) {
            int cn = n0 + tx * 4 + j;
            float v = acc[i][j] + bias[cn];
            if (res) v += res[(size_t)r * NN + cn];
            if (epi) v = gelu_tanh(v);
            C[(size_t)r * NN + cn] = v;
        }
    }
}

// ---------------- rope in-place on qkv buffer ----------------
__global__ void rope_kernel(float* __restrict__ qkv) {
    int id = blockIdx.x * blockDim.x + threadIdx.x;
    if (id >= NTOK * NHEAD * HALFK) return;
    int n = id / (NHEAD * HALFK);
    int rest = id % (NHEAD * HALFK);
    int h = rest / HALFK, i = rest % HALFK;
    float c = g_cos[n * HALFK + i], s = g_sin[n * HALFK + i];
    size_t base = (size_t)n * (3 * DMODEL) + h * KDIM;
    float* q = qkv + base;
    float* k = qkv + base + DMODEL;
    float q1 = q[i], q2 = q[i + HALFK];
    q[i] = q1 * c - q2 * s;
    q[i + HALFK] = q2 * c + q1 * s;
    float k1 = k[i], k2 = k[i + HALFK];
    k[i] = k1 * c - k2 * s;
    k[i + HALFK] = k2 * c + k1 * s;
}

// ---------------- scores: S[h][q][j] = scale * q . k  (batched per (img,h)) ----------------
__global__ void scores_kernel(const float* __restrict__ qkv, float* __restrict__ S) {
    int b = blockIdx.z;
    int h = b & 15, img = b >> 4;
    const float* Q = qkv + (size_t)img * TPI * (3 * DMODEL) + h * KDIM;
    const float* Kp = Q + DMODEL;
    float* C = S + (size_t)h * NTOK * TPI + (size_t)img * TPI * TPI;
    __shared__ float As[16][64];
    __shared__ float Bs[16][64];
    const int tid = threadIdx.x;
    const int tx = tid & 15, ty = tid >> 4;
    const int m0 = blockIdx.y * 64, n0 = blockIdx.x * 64;
    const int lm = tid >> 2, lk = (tid & 3) << 2;
    float acc[4][4] = {};
    for (int k0 = 0; k0 < KDIM; k0 += 16) {
        float4 a = *(const float4*)(Q + (size_t)(m0 + lm) * (3 * DMODEL) + k0 + lk);
        As[lk + 0][lm] = a.x; As[lk + 1][lm] = a.y;
        As[lk + 2][lm] = a.z; As[lk + 3][lm] = a.w;
        float4 bb = *(const float4*)(Kp + (size_t)(n0 + lm) * (3 * DMODEL) + k0 + lk);
        Bs[lk + 0][lm] = bb.x; Bs[lk + 1][lm] = bb.y;
        Bs[lk + 2][lm] = bb.z; Bs[lk + 3][lm] = bb.w;
        __syncthreads();
        #pragma unroll
        for (int k = 0; k < 16; ++k) {
            float av[4], bv[4];
            #pragma unroll
            for (int i = 0; i < 4; ++i) av[i] = As[k][ty * 4 + i];
            #pragma unroll
            for (int j = 0; j < 4; ++j) bv[j] = Bs[k][tx * 4 + j];
            #pragma unroll
            for (int i = 0; i < 4; ++i)
                #pragma unroll
                for (int j = 0; j < 4; ++j)
                    acc[i][j] = fmaf(av[i], bv[j], acc[i][j]);
        }
        __syncthreads();
    }
    const float scale = 0.11180339887498949f;  // 80^-0.5
    #pragma unroll
    for (int i = 0; i < 4; ++i)
        #pragma unroll
        for (int j = 0; j < 4; ++j)
            C[(size_t)(m0 + ty * 4 + i) * TPI + n0 + tx * 4 + j] = acc[i][j] * scale;
}

// ---------------- row softmax over 512 ----------------
__global__ void softmax_kernel(float* __restrict__ S) {
    float* row = S + (size_t)blockIdx.x * TPI;
    int tid = threadIdx.x;  // 128
    float4 v = ((float4*)row)[tid];
    float m = fmaxf(fmaxf(v.x, v.y), fmaxf(v.z, v.w));
    m = warp_max(m);
    __shared__ float sm[4], ss[4];
    if ((tid & 31) == 0) sm[tid >> 5] = m;
    __syncthreads();
    m = fmaxf(fmaxf(sm[0], sm[1]), fmaxf(sm[2], sm[3]));
    v.x = expf(v.x - m); v.y = expf(v.y - m);
    v.z = expf(v.z - m); v.w = expf(v.w - m);
    float s = v.x + v.y + v.z + v.w;
    s = warp_sum(s);
    if ((tid & 31) == 0) ss[tid >> 5] = s;
    __syncthreads();
    float inv = 1.0f / (ss[0] + ss[1] + ss[2] + ss[3]);
    v.x *= inv; v.y *= inv; v.z *= inv; v.w *= inv;
    ((float4*)row)[tid] = v;
}

// ---------------- o = attn @ V (batched per (img,h)), 64x80 tile ----------------
__global__ void av_kernel(const float* __restrict__ S, const float* __restrict__ qkv,
                          float* __restrict__ o) {
    int b = blockIdx.z;
    int h = b & 15, img = b >> 4;
    const float* P = S + (size_t)h * NTOK * TPI + (size_t)img * TPI * TPI;
    const float* V = qkv + (size_t)img * TPI * (3 * DMODEL) + 2 * DMODEL + h * KDIM;
    __shared__ float Ps[16][64];
    __shared__ float Vs[16][80];
    const int tid = threadIdx.x;
    const int tx = tid & 15, ty = tid >> 4;
    const int m0 = blockIdx.x * 64;
    const int lm = tid >> 2, lk = (tid & 3) << 2;
    float acc[4][5] = {};
    for (int k0 = 0; k0 < TPI; k0 += 16) {
        float4 a = *(const float4*)(P + (size_t)(m0 + lm) * TPI + k0 + lk);
        Ps[lk + 0][lm] = a.x; Ps[lk + 1][lm] = a.y;
        Ps[lk + 2][lm] = a.z; Ps[lk + 3][lm] = a.w;
        #pragma unroll
        for (int i = 0; i < 5; ++i) {
            int e = i * 256 + tid;          // 16*80 = 1280 elements
            int kk = e / 80, nn = e % 80;
            Vs[kk][nn] = V[(size_t)(k0 + kk) * (3 * DMODEL) + nn];
        }
        __syncthreads();
        #pragma unroll
        for (int k = 0; k < 16; ++k) {
            float av[4], bv[5];
            #pragma unroll
            for (int i = 0; i < 4; ++i) av[i] = Ps[k][ty * 4 + i];
            #pragma unroll
            for (int j = 0; j < 5; ++j) bv[j] = Vs[k][tx * 5 + j];
            #pragma unroll
            for (int i = 0; i < 4; ++i)
                #pragma unroll
                for (int j = 0; j < 5; ++j)
                    acc[i][j] = fmaf(av[i], bv[j], acc[i][j]);
        }
        __syncthreads();
    }
    #pragma unroll
    for (int i = 0; i < 4; ++i) {
        size_t r = (size_t)(img * TPI + m0 + ty * 4 + i) * DMODEL + h * KDIM;
        #pragma unroll
        for (int j = 0; j < 5; ++j)
            o[r + tx * 5 + j] = acc[i][j];
    }
}

// ---------------- launch ----------------
extern "C" void kernel_launch(void* const* d_in, const int* in_sizes, int n_in,
                              void* d_out, int out_size) {
    const float* pixels   = (const float*)d_in[0];
    const int*   grid_thw = (const int*)d_in[1];
    const float* pos_embed= (const float*)d_in[2];
    const float* patch_w  = (const float*)d_in[3];
    const float* patch_b  = (const float*)d_in[4];
    const float* ln1_s    = (const float*)d_in[5];
    const float* ln1_b    = (const float*)d_in[6];
    const float* qkv_w    = (const float*)d_in[7];
    const float* qkv_b    = (const float*)d_in[8];
    const float* proj_w   = (const float*)d_in[9];
    const float* proj_b   = (const float*)d_in[10];
    const float* ln2_s    = (const float*)d_in[11];
    const float* ln2_b    = (const float*)d_in[12];
    const float* fc1_w    = (const float*)d_in[13];
    const float* fc1_b    = (const float*)d_in[14];
    const float* fc2_w    = (const float*)d_in[15];
    const float* fc2_b    = (const float*)d_in[16];
    const float* mn_s     = (const float*)d_in[17];
    const float* mn_b     = (const float*)d_in[18];
    const float* mfc1_w   = (const float*)d_in[19];
    const float* mfc1_b   = (const float*)d_in[20];
    const float* mfc2_w   = (const float*)d_in[21];
    const float* mfc2_b   = (const float*)d_in[22];
    float* out = (float*)d_out;

    float *px, *phdn, *pqkv, *pS, *pobuf, *pff;
    cudaGetSymbolAddress((void**)&px, g_x);
    cudaGetSymbolAddress((void**)&phdn, g_hdn);
    cudaGetSymbolAddress((void**)&pqkv, g_qkv);
    cudaGetSymbolAddress((void**)&pS, g_scores);
    cudaGetSymbolAddress((void**)&pobuf, g_obuf);
    cudaGetSymbolAddress((void**)&pff, g_ff);

    int n_imgs = in_sizes[1] / 3;

    coords_kernel<<<(NTOK + 255) / 256, 256>>>(grid_thw, n_imgs);
    ropetab_kernel<<<(NTOK * HALFK + 255) / 256, 256>>>();

    // patch embed: x = pixels @ patch_w + patch_b   (2048 x 1280, K=1536)
    gemm_kernel<<<dim3(DMODEL / 64, NTOK / 64), 256>>>(
        pixels, patch_w, patch_b, nullptr, px, NTOK, DMODEL, 1536, 0);
    posembed_kernel<<<NTOK, 256>>>(pos_embed, px);

    for (int l = 0; l < NLAYER; ++l) {
        layernorm_kernel<<<NTOK, 256>>>(px, ln1_s + l * DMODEL, ln1_b + l * DMODEL, phdn, DMODEL);
        gemm_kernel<<<dim3(3 * DMODEL / 64, NTOK / 64), 256>>>(
            phdn, qkv_w + (size_t)l * DMODEL * 3 * DMODEL, qkv_b + l * 3 * DMODEL,
            nullptr, pqkv, NTOK, 3 * DMODEL, DMODEL, 0);
        rope_kernel<<<(NTOK * NHEAD * HALFK + 255) / 256, 256>>>(pqkv);
        scores_kernel<<<dim3(TPI / 64, TPI / 64, NHEAD * NIMG), 256>>>(pqkv, pS);
        softmax_kernel<<<NHEAD * NTOK, 128>>>(pS);
        av_kernel<<<dim3(TPI / 64, 1, NHEAD * NIMG), 256>>>(pS, pqkv, pobuf);
        gemm_kernel<<<dim3(DMODEL / 64, NTOK / 64), 256>>>(
            pobuf, proj_w + (size_t)l * DMODEL * DMODEL, proj_b + l * DMODEL,
            px, px, NTOK, DMODEL, DMODEL, 0);
        layernorm_kernel<<<NTOK, 256>>>(px, ln2_s + l * DMODEL, ln2_b + l * DMODEL, phdn, DMODEL);
        gemm_kernel<<<dim3(FDIM / 64, NTOK / 64), 256>>>(
            phdn, fc1_w + (size_t)l * DMODEL * FDIM, fc1_b + l * FDIM,
            nullptr, pff, NTOK, FDIM, DMODEL, 1);
        gemm_kernel<<<dim3(DMODEL / 64, NTOK / 64), 256>>>(
            pff, fc2_w + (size_t)l * FDIM * DMODEL, fc2_b + l * DMODEL,
            px, px, NTOK, DMODEL, FDIM, 0);
    }

    // merger
    layernorm_kernel<<<NTOK, 256>>>(px, mn_s, mn_b, phdn, DMODEL);
    // reshape (2048,1280) -> (512,5120) is a no-op on row-major memory
    gemm_kernel<<<dim3(FDIM / 64, (NTOK / 4) / 64), 256>>>(
        phdn, mfc1_w, mfc1_b, nullptr, pff, NTOK / 4, FDIM, FDIM, 1);
    gemm_kernel<<<dim3(OUTD / 64, (NTOK / 4) / 64), 256>>>(
        pff, mfc2_w, mfc2_b, nullptr, out, NTOK / 4, OUTD, FDIM, 0);
}

// round 2
// speedup vs baseline: 2.4816x; 2.4816x over previous
#include <cuda_runtime.h>
#include <cuda_bf16.h>
#include <cstddef>
#include <cstdint>

// ---------------- fixed problem constants ----------------
#define NTOK 2048
#define DMODEL 1280
#define NHEAD 16
#define KDIM 80
#define HALFK 40
#define NLAYER 4
#define FDIM 5120
#define GPOS 48
#define OUTD 2048
#define TPI 512      // tokens per image (1*16*32)
#define NIMG 4

// ---------------- scratch (device globals; no runtime alloc) ----------------
__device__ float g_x[NTOK * DMODEL];
__device__ float g_hdn[NTOK * DMODEL];
__device__ float g_qkv[NTOK * 3 * DMODEL];
__device__ float g_scores[(size_t)NHEAD * NTOK * TPI];   // 64 MB
__device__ float g_obuf[NTOK * DMODEL];
__device__ float g_ff[NTOK * FDIM];                      // 40 MB
__device__ float g_cos[NTOK * HALFK];
__device__ float g_sin[NTOK * HALFK];
__device__ int g_row[NTOK], g_col[NTOK], g_h[NTOK], g_w[NTOK];

// ---------------- helpers ----------------
__device__ __forceinline__ float gelu_tanh(float v) {
    const float c = 0.7978845608028654f;
    float t = tanhf(c * (v + 0.044715f * v * v * v));
    return 0.5f * v * (1.0f + t);
}
__device__ __forceinline__ float warp_sum(float v) {
    #pragma unroll
    for (int o = 16; o > 0; o >>= 1) v += __shfl_xor_sync(0xffffffffu, v, o);
    return v;
}
__device__ __forceinline__ float warp_max(float v) {
    #pragma unroll
    for (int o = 16; o > 0; o >>= 1) v = fmaxf(v, __shfl_xor_sync(0xffffffffu, v, o));
    return v;
}
__device__ __forceinline__ uint32_t f2tf32(float f) {
    uint32_t r;
    asm("cvt.rna.tf32.f32 %0, %1;" : "=r"(r) : "f"(f));
    return r;
}
__device__ __forceinline__ void mma_tf32(float& c0, float& c1, float& c2, float& c3,
                                         uint32_t a0, uint32_t a1, uint32_t a2, uint32_t a3,
                                         uint32_t b0, uint32_t b1) {
    asm volatile(
        "mma.sync.aligned.m16n8k8.row.col.f32.tf32.tf32.f32 "
        "{%0,%1,%2,%3}, {%4,%5,%6,%7}, {%8,%9}, {%0,%1,%2,%3};"
        : "+f"(c0), "+f"(c1), "+f"(c2), "+f"(c3)
        : "r"(a0), "r"(a1), "r"(a2), "r"(a3), "r"(b0), "r"(b1));
}

// ---------------- token coords ----------------
__global__ void coords_kernel(const int* __restrict__ grid, int n_imgs) {
    int t = blockIdx.x * blockDim.x + threadIdx.x;
    if (t >= NTOK) return;
    int acc = 0, local = 0, h = 1, w = 1;
    for (int i = 0; i < n_imgs; i++) {
        int tpi = grid[i * 3] * grid[i * 3 + 1] * grid[i * 3 + 2];
        if (t >= acc && t < acc + tpi) {
            local = t - acc; h = grid[i * 3 + 1]; w = grid[i * 3 + 2];
        }
        acc += tpi;
    }
    int spatial = local % (h * w);
    int group = spatial / 4, intra = spatial % 4;   // merge_size = 2
    int mw = w / 2;
    g_row[t] = (group / mw) * 2 + intra / 2;
    g_col[t] = (group % mw) * 2 + intra % 2;
    g_h[t] = h; g_w[t] = w;
}

// ---------------- rope cos/sin table ----------------
__global__ void ropetab_kernel() {
    int id = blockIdx.x * blockDim.x + threadIdx.x;
    if (id >= NTOK * HALFK) return;
    int n = id / HALFK, j = id % HALFK;
    int jj = j % 20;
    float pos = (float)((j < 20) ? g_row[n] : g_col[n]);
    float inv_freq = powf(10000.0f, -(float)jj / 20.0f);
    float f = pos * inv_freq;
    g_cos[id] = cosf(f);
    g_sin[id] = sinf(f);
}

// ---------------- bilinear pos-embed add ----------------
__global__ void posembed_kernel(const float* __restrict__ pos_embed, float* __restrict__ x) {
    int n = blockIdx.x;
    int row = g_row[n], col = g_col[n], h = g_h[n], w = g_w[n];
    float rf = (h > 1) ? (float)row * (float)(GPOS - 1) / (float)(h - 1 > 1 ? h - 1 : 1) : 0.0f;
    float cf = (w > 1) ? (float)col * (float)(GPOS - 1) / (float)(w - 1 > 1 ? w - 1 : 1) : 0.0f;
    int r0 = (int)floorf(rf), c0 = (int)floorf(cf);
    int r1 = min(r0 + 1, GPOS - 1), c1 = min(c0 + 1, GPOS - 1);
    float wr = rf - (float)r0, wc = cf - (float)c0;
    float w00 = (1 - wr) * (1 - wc), w01 = (1 - wr) * wc, w10 = wr * (1 - wc), w11 = wr * wc;
    const float* p00 = pos_embed + (size_t)(r0 * GPOS + c0) * DMODEL;
    const float* p01 = pos_embed + (size_t)(r0 * GPOS + c1) * DMODEL;
    const float* p10 = pos_embed + (size_t)(r1 * GPOS + c0) * DMODEL;
    const float* p11 = pos_embed + (size_t)(r1 * GPOS + c1) * DMODEL;
    float* xr = x + (size_t)n * DMODEL;
    for (int d = threadIdx.x; d < DMODEL; d += blockDim.x)
        xr[d] += p00[d] * w00 + p01[d] * w01 + p10[d] * w10 + p11[d] * w11;
}

// ---------------- two-pass layernorm ----------------
__global__ void layernorm_kernel(const float* __restrict__ x, const float* __restrict__ s,
                                 const float* __restrict__ b, float* __restrict__ out, int cols) {
    int r = blockIdx.x, tid = threadIdx.x;
    const float* xr = x + (size_t)r * cols;
    __shared__ float red[8];
    float sum = 0.0f;
    for (int c = tid; c < cols; c += 256) sum += xr[c];
    sum = warp_sum(sum);
    if ((tid & 31) == 0) red[tid >> 5] = sum;
    __syncthreads();
    float tot = 0.0f;
    #pragma unroll
    for (int i = 0; i < 8; i++) tot += red[i];
    float mu = tot / (float)cols;
    __syncthreads();
    float vs = 0.0f;
    for (int c = tid; c < cols; c += 256) { float d = xr[c] - mu; vs += d * d; }
    vs = warp_sum(vs);
    if ((tid & 31) == 0) red[tid >> 5] = vs;
    __syncthreads();
    float vtot = 0.0f;
    #pragma unroll
    for (int i = 0; i < 8; i++) vtot += red[i];
    float inv = rsqrtf(vtot / (float)cols + 1e-6f);
    float* orow = out + (size_t)r * cols;
    for (int c = tid; c < cols; c += 256)
        orow[c] = (xr[c] - mu) * inv * s[c] + b[c];
}

// ---------------- tf32 tensor-core GEMM: C = A @ W + bias (+res) (+gelu) ----------------
// MM % 128 == 0, NN % 128 == 0, KK % 32 == 0
// Block tile 128x128, K-tile 32, 256 threads = 8 warps (2m x 4n), warp tile 64x32.
#define AP 36   // A smem row stride (32 + 4 pad)
#define BP 132  // B smem row stride (128 + 4 pad)
__global__ void __launch_bounds__(256)
tf32_gemm(const float* __restrict__ A, const float* __restrict__ W,
          const float* __restrict__ bias, const float* __restrict__ res,
          float* __restrict__ C, int MM, int NN, int KK, int epi) {
    __shared__ float As[128 * AP];
    __shared__ float Bs[32 * BP];
    const int tid = threadIdx.x;
    const int warp = tid >> 5, lane = tid & 31;
    const int wm = warp & 1, wn = warp >> 1;     // warp tile: rows wm*64, cols wn*32
    const int g = lane >> 2, c = lane & 3;
    const int m0 = blockIdx.y * 128, n0 = blockIdx.x * 128;

    // global loader indices
    const int arow = tid >> 3, acol = (tid & 7) << 2;    // A: 128 rows x 8 float4, 4 iters
    const int brow = tid >> 5, bcol = (tid & 31) << 2;   // B: 32 rows x 32 float4, 4 iters

    float4 ra[4], rb[4];
    const uint32_t* Asb = reinterpret_cast<const uint32_t*>(As);
    const uint32_t* Bsb = reinterpret_cast<const uint32_t*>(Bs);

    float acc[4][4][4];
    #pragma unroll
    for (int i = 0; i < 4; i++)
        #pragma unroll
        for (int j = 0; j < 4; j++)
            #pragma unroll
            for (int r = 0; r < 4; r++) acc[i][j][r] = 0.0f;

    // prefetch first tile
    #pragma unroll
    for (int i = 0; i < 4; i++) {
        ra[i] = *(const float4*)(A + (size_t)(m0 + arow + i * 32) * KK + acol);
        rb[i] = *(const float4*)(W + (size_t)(brow + i * 8) * NN + n0 + bcol);
    }

    for (int k0 = 0; k0 < KK; k0 += 32) {
        // store prefetched regs -> smem with tf32 rounding
        #pragma unroll
        for (int i = 0; i < 4; i++) {
            float* pa = As + (arow + i * 32) * AP + acol;
            pa[0] = __uint_as_float(f2tf32(ra[i].x));
            pa[1] = __uint_as_float(f2tf32(ra[i].y));
            pa[2] = __uint_as_float(f2tf32(ra[i].z));
            pa[3] = __uint_as_float(f2tf32(ra[i].w));
            float* pb = Bs + (brow + i * 8) * BP + bcol;
            pb[0] = __uint_as_float(f2tf32(rb[i].x));
            pb[1] = __uint_as_float(f2tf32(rb[i].y));
            pb[2] = __uint_as_float(f2tf32(rb[i].z));
            pb[3] = __uint_as_float(f2tf32(rb[i].w));
        }
        __syncthreads();
        // prefetch next tile
        if (k0 + 32 < KK) {
            #pragma unroll
            for (int i = 0; i < 4; i++) {
                ra[i] = *(const float4*)(A + (size_t)(m0 + arow + i * 32) * KK + k0 + 32 + acol);
                rb[i] = *(const float4*)(W + (size_t)(brow + i * 8 + (k0 + 32) / 1) * 0 +
                                         (size_t)(k0 + 32 + brow + i * 8) * NN + n0 + bcol);
            }
        }
        // compute 4 k-steps
        #pragma unroll
        for (int kk = 0; kk < 4; kk++) {
            const int kb = kk * 8;
            uint32_t af[4][4];
            #pragma unroll
            for (int mi = 0; mi < 4; mi++) {
                int r = wm * 64 + mi * 16;
                af[mi][0] = Asb[(r + g) * AP + kb + c];
                af[mi][1] = Asb[(r + g + 8) * AP + kb + c];
                af[mi][2] = Asb[(r + g) * AP + kb + c + 4];
                af[mi][3] = Asb[(r + g + 8) * AP + kb + c + 4];
            }
            uint32_t bf[4][2];
            #pragma unroll
            for (int ni = 0; ni < 4; ni++) {
                int col = wn * 32 + ni * 8;
                bf[ni][0] = Bsb[(kb + c) * BP + col + g];
                bf[ni][1] = Bsb[(kb + c + 4) * BP + col + g];
            }
            #pragma unroll
            for (int mi = 0; mi < 4; mi++)
                #pragma unroll
                for (int ni = 0; ni < 4; ni++)
                    mma_tf32(acc[mi][ni][0], acc[mi][ni][1], acc[mi][ni][2], acc[mi][ni][3],
                             af[mi][0], af[mi][1], af[mi][2], af[mi][3],
                             bf[ni][0], bf[ni][1]);
        }
        __syncthreads();
    }

    // epilogue
    #pragma unroll
    for (int mi = 0; mi < 4; mi++) {
        #pragma unroll
        for (int ni = 0; ni < 4; ni++) {
            int r0r = m0 + wm * 64 + mi * 16 + g;
            int cn = n0 + wn * 32 + ni * 8 + 2 * c;
            #pragma unroll
            for (int half = 0; half < 2; half++) {
                int r = r0r + half * 8;
                float v0 = acc[mi][ni][half * 2 + 0] + bias[cn];
                float v1 = acc[mi][ni][half * 2 + 1] + bias[cn + 1];
                if (res) {
                    v0 += res[(size_t)r * NN + cn];
                    v1 += res[(size_t)r * NN + cn + 1];
                }
                if (epi) { v0 = gelu_tanh(v0); v1 = gelu_tanh(v1); }
                float2 o = make_float2(v0, v1);
                *(float2*)(C + (size_t)r * NN + cn) = o;
            }
        }
    }
}

// ---------------- rope in-place on qkv buffer ----------------
__global__ void rope_kernel(float* __restrict__ qkv) {
    int id = blockIdx.x * blockDim.x + threadIdx.x;
    if (id >= NTOK * NHEAD * HALFK) return;
    int n = id / (NHEAD * HALFK);
    int rest = id % (NHEAD * HALFK);
    int h = rest / HALFK, i = rest % HALFK;
    float c = g_cos[n * HALFK + i], s = g_sin[n * HALFK + i];
    size_t base = (size_t)n * (3 * DMODEL) + h * KDIM;
    float* q = qkv + base;
    float* k = qkv + base + DMODEL;
    float q1 = q[i], q2 = q[i + HALFK];
    q[i] = q1 * c - q2 * s;
    q[i + HALFK] = q2 * c + q1 * s;
    float k1 = k[i], k2 = k[i + HALFK];
    k[i] = k1 * c - k2 * s;
    k[i + HALFK] = k2 * c + k1 * s;
}

// ---------------- scores: S[h][q][j] = scale * q . k  (batched per (img,h)) ----------------
__global__ void scores_kernel(const float* __restrict__ qkv, float* __restrict__ S) {
    int b = blockIdx.z;
    int h = b & 15, img = b >> 4;
    const float* Q = qkv + (size_t)img * TPI * (3 * DMODEL) + h * KDIM;
    const float* Kp = Q + DMODEL;
    float* C = S + (size_t)h * NTOK * TPI + (size_t)img * TPI * TPI;
    __shared__ float As[16][64];
    __shared__ float Bs[16][64];
    const int tid = threadIdx.x;
    const int tx = tid & 15, ty = tid >> 4;
    const int m0 = blockIdx.y * 64, n0 = blockIdx.x * 64;
    const int lm = tid >> 2, lk = (tid & 3) << 2;
    float acc[4][4] = {};
    for (int k0 = 0; k0 < KDIM; k0 += 16) {
        float4 a = *(const float4*)(Q + (size_t)(m0 + lm) * (3 * DMODEL) + k0 + lk);
        As[lk + 0][lm] = a.x; As[lk + 1][lm] = a.y;
        As[lk + 2][lm] = a.z; As[lk + 3][lm] = a.w;
        float4 bb = *(const float4*)(Kp + (size_t)(n0 + lm) * (3 * DMODEL) + k0 + lk);
        Bs[lk + 0][lm] = bb.x; Bs[lk + 1][lm] = bb.y;
        Bs[lk + 2][lm] = bb.z; Bs[lk + 3][lm] = bb.w;
        __syncthreads();
        #pragma unroll
        for (int k = 0; k < 16; ++k) {
            float av[4], bv[4];
            #pragma unroll
            for (int i = 0; i < 4; ++i) av[i] = As[k][ty * 4 + i];
            #pragma unroll
            for (int j = 0; j < 4; ++j) bv[j] = Bs[k][tx * 4 + j];
            #pragma unroll
            for (int i = 0; i < 4; ++i)
                #pragma unroll
                for (int j = 0; j < 4; ++j)
                    acc[i][j] = fmaf(av[i], bv[j], acc[i][j]);
        }
        __syncthreads();
    }
    const float scale = 0.11180339887498949f;  // 80^-0.5
    #pragma unroll
    for (int i = 0; i < 4; ++i)
        #pragma unroll
        for (int j = 0; j < 4; ++j)
            C[(size_t)(m0 + ty * 4 + i) * TPI + n0 + tx * 4 + j] = acc[i][j] * scale;
}

// ---------------- row softmax over 512 ----------------
__global__ void softmax_kernel(float* __restrict__ S) {
    float* row = S + (size_t)blockIdx.x * TPI;
    int tid = threadIdx.x;  // 128
    float4 v = ((float4*)row)[tid];
    float m = fmaxf(fmaxf(v.x, v.y), fmaxf(v.z, v.w));
    m = warp_max(m);
    __shared__ float sm[4], ss[4];
    if ((tid & 31) == 0) sm[tid >> 5] = m;
    __syncthreads();
    m = fmaxf(fmaxf(sm[0], sm[1]), fmaxf(sm[2], sm[3]));
    v.x = expf(v.x - m); v.y = expf(v.y - m);
    v.z = expf(v.z - m); v.w = expf(v.w - m);
    float s = v.x + v.y + v.z + v.w;
    s = warp_sum(s);
    if ((tid & 31) == 0) ss[tid >> 5] = s;
    __syncthreads();
    float inv = 1.0f / (ss[0] + ss[1] + ss[2] + ss[3]);
    v.x *= inv; v.y *= inv; v.z *= inv; v.w *= inv;
    ((float4*)row)[tid] = v;
}

// ---------------- o = attn @ V (batched per (img,h)), 64x80 tile ----------------
__global__ void av_kernel(const float* __restrict__ S, const float* __restrict__ qkv,
                          float* __restrict__ o) {
    int b = blockIdx.z;
    int h = b & 15, img = b >> 4;
    const float* P = S + (size_t)h * NTOK * TPI + (size_t)img * TPI * TPI;
    const float* V = qkv + (size_t)img * TPI * (3 * DMODEL) + 2 * DMODEL + h * KDIM;
    __shared__ float Ps[16][64];
    __shared__ float Vs[16][80];
    const int tid = threadIdx.x;
    const int tx = tid & 15, ty = tid >> 4;
    const int m0 = blockIdx.x * 64;
    const int lm = tid >> 2, lk = (tid & 3) << 2;
    float acc[4][5] = {};
    for (int k0 = 0; k0 < TPI; k0 += 16) {
        float4 a = *(const float4*)(P + (size_t)(m0 + lm) * TPI + k0 + lk);
        Ps[lk + 0][lm] = a.x; Ps[lk + 1][lm] = a.y;
        Ps[lk + 2][lm] = a.z; Ps[lk + 3][lm] = a.w;
        #pragma unroll
        for (int i = 0; i < 5; ++i) {
            int e = i * 256 + tid;          // 16*80 = 1280 elements
            int kk = e / 80, nn = e % 80;
            Vs[kk][nn] = V[(size_t)(k0 + kk) * (3 * DMODEL) + nn];
        }
        __syncthreads();
        #pragma unroll
        for (int k = 0; k < 16; ++k) {
            float av[4], bv[5];
            #pragma unroll
            for (int i = 0; i < 4; ++i) av[i] = Ps[k][ty * 4 + i];
            #pragma unroll
            for (int j = 0; j < 5; ++j) bv[j] = Vs[k][tx * 5 + j];
            #pragma unroll
            for (int i = 0; i < 4; ++i)
                #pragma unroll
                for (int j = 0; j < 5; ++j)
                    acc[i][j] = fmaf(av[i], bv[j], acc[i][j]);
        }
        __syncthreads();
    }
    #pragma unroll
    for (int i = 0; i < 4; ++i) {
        size_t r = (size_t)(img * TPI + m0 + ty * 4 + i) * DMODEL + h * KDIM;
        #pragma unroll
        for (int j = 0; j < 5; ++j)
            o[r + tx * 5 + j] = acc[i][j];
    }
}

// ---------------- launch ----------------
extern "C" void kernel_launch(void* const* d_in, const int* in_sizes, int n_in,
                              void* d_out, int out_size) {
    const float* pixels   = (const float*)d_in[0];
    const int*   grid_thw = (const int*)d_in[1];
    const float* pos_embed= (const float*)d_in[2];
    const float* patch_w  = (const float*)d_in[3];
    const float* patch_b  = (const float*)d_in[4];
    const float* ln1_s    = (const float*)d_in[5];
    const float* ln1_b    = (const float*)d_in[6];
    const float* qkv_w    = (const float*)d_in[7];
    const float* qkv_b    = (const float*)d_in[8];
    const float* proj_w   = (const float*)d_in[9];
    const float* proj_b   = (const float*)d_in[10];
    const float* ln2_s    = (const float*)d_in[11];
    const float* ln2_b    = (const float*)d_in[12];
    const float* fc1_w    = (const float*)d_in[13];
    const float* fc1_b    = (const float*)d_in[14];
    const float* fc2_w    = (const float*)d_in[15];
    const float* fc2_b    = (const float*)d_in[16];
    const float* mn_s     = (const float*)d_in[17];
    const float* mn_b     = (const float*)d_in[18];
    const float* mfc1_w   = (const float*)d_in[19];
    const float* mfc1_b   = (const float*)d_in[20];
    const float* mfc2_w   = (const float*)d_in[21];
    const float* mfc2_b   = (const float*)d_in[22];
    float* out = (float*)d_out;

    float *px, *phdn, *pqkv, *pS, *pobuf, *pff;
    cudaGetSymbolAddress((void**)&px, g_x);
    cudaGetSymbolAddress((void**)&phdn, g_hdn);
    cudaGetSymbolAddress((void**)&pqkv, g_qkv);
    cudaGetSymbolAddress((void**)&pS, g_scores);
    cudaGetSymbolAddress((void**)&pobuf, g_obuf);
    cudaGetSymbolAddress((void**)&pff, g_ff);

    int n_imgs = in_sizes[1] / 3;

    coords_kernel<<<(NTOK + 255) / 256, 256>>>(grid_thw, n_imgs);
    ropetab_kernel<<<(NTOK * HALFK + 255) / 256, 256>>>();

    // patch embed: x = pixels @ patch_w + patch_b   (2048 x 1280, K=1536)
    tf32_gemm<<<dim3(DMODEL / 128, NTOK / 128), 256>>>(
        pixels, patch_w, patch_b, nullptr, px, NTOK, DMODEL, 1536, 0);
    posembed_kernel<<<NTOK, 256>>>(pos_embed, px);

    for (int l = 0; l < NLAYER; ++l) {
        layernorm_kernel<<<NTOK, 256>>>(px, ln1_s + l * DMODEL, ln1_b + l * DMODEL, phdn, DMODEL);
        tf32_gemm<<<dim3(3 * DMODEL / 128, NTOK / 128), 256>>>(
            phdn, qkv_w + (size_t)l * DMODEL * 3 * DMODEL, qkv_b + l * 3 * DMODEL,
            nullptr, pqkv, NTOK, 3 * DMODEL, DMODEL, 0);
        rope_kernel<<<(NTOK * NHEAD * HALFK + 255) / 256, 256>>>(pqkv);
        scores_kernel<<<dim3(TPI / 64, TPI / 64, NHEAD * NIMG), 256>>>(pqkv, pS);
        softmax_kernel<<<NHEAD * NTOK, 128>>>(pS);
        av_kernel<<<dim3(TPI / 64, 1, NHEAD * NIMG), 256>>>(pS, pqkv, pobuf);
        tf32_gemm<<<dim3(DMODEL / 128, NTOK / 128), 256>>>(
            pobuf, proj_w + (size_t)l * DMODEL * DMODEL, proj_b + l * DMODEL,
            px, px, NTOK, DMODEL, DMODEL, 0);
        layernorm_kernel<<<NTOK, 256>>>(px, ln2_s + l * DMODEL, ln2_b + l * DMODEL, phdn, DMODEL);
        tf32_gemm<<<dim3(FDIM / 128, NTOK / 128), 256>>>(
            phdn, fc1_w + (size_t)l * DMODEL * FDIM, fc1_b + l * FDIM,
            nullptr, pff, NTOK, FDIM, DMODEL, 1);
        tf32_gemm<<<dim3(DMODEL / 128, NTOK / 128), 256>>>(
            pff, fc2_w + (size_t)l * FDIM * DMODEL, fc2_b + l * DMODEL,
            px, px, NTOK, DMODEL, FDIM, 0);
    }

    // merger
    layernorm_kernel<<<NTOK, 256>>>(px, mn_s, mn_b, phdn, DMODEL);
    // reshape (2048,1280) -> (512,5120) is a no-op on row-major memory
    tf32_gemm<<<dim3(FDIM / 128, (NTOK / 4) / 128), 256>>>(
        phdn, mfc1_w, mfc1_b, nullptr, pff, NTOK / 4, FDIM, FDIM, 1);
    tf32_gemm<<<dim3(OUTD / 128, (NTOK / 4) / 128), 256>>>(
        pff, mfc2_w, mfc2_b, nullptr, out, NTOK / 4, OUTD, FDIM, 0);
}